// round 5
// baseline (speedup 1.0000x reference)
#include <cuda_runtime.h>
#include <math.h>

// dag[i,j] closed form (reference scan collapses; ST forward == hard sample):
//   b[i,j]  = (e + g0) > (1 - e + g1)
//   nr[j]   = !((rp[j] + gr0[j]) > (1 - rp[j] + gr1[j]))
//   dag[i,j] = 0                               (i == j)
//            = b[i,j]*nr[j]                    (j > i)
//            = b[i,j]*nr[j]*(1 - b[j,i]*nr[i]) (j < i)
//
// TILE=64 tile pairs, triangular grid (528 blocks for n=2048) -> fits in a
// single wave at 4 blocks/SM. Q-phase loads issued before the barrier.

#define TILE 64

__device__ __forceinline__ int tri_row(int bid, int T) {
    // Find bi such that off(bi) <= bid < off(bi+1), off(b) = b*T - b*(b-1)/2.
    double d = (2.0 * T + 1.0);
    int bi = (int)floor((d - sqrt(d * d - 8.0 * (double)bid)) * 0.5);
    if (bi < 0) bi = 0;
    if (bi > T - 1) bi = T - 1;
    // exact fixup, at most one step each way
    if ((bi + 1) * T - ((bi + 1) * bi) / 2 <= bid) bi++;
    else if (bi * T - (bi * (bi - 1)) / 2 > bid) bi--;
    return bi;
}

__global__ __launch_bounds__(256, 4) void dag_pair_kernel(
    const float*  __restrict__ rootp,   // (n)
    const float4* __restrict__ edgep4,  // (n, n/4)
    const float2* __restrict__ groot,   // (n) float2
    const float4* __restrict__ gedge4,  // (n, n/2) float4 = 2 cols
    float4*       __restrict__ out4,    // (n, n/4)
    int n, int T)                        // T = n/TILE
{
    const int bid = blockIdx.x;
    const int bi = tri_row(bid, T);
    const int bj = bi + (bid - (bi * T - (bi * (bi - 1)) / 2));

    const int tid = threadIdx.x;
    const int tx  = tid & 15;          // 0..15 col group
    const int ty  = tid >> 4;          // 0..15 base row
    const int c4  = tx << 2;           // 0,4,...,60
    const bool diag = (bi == bj);

    const int n4 = n >> 2;
    const int n2 = n >> 1;

    __shared__ float vP[TILE][TILE + 1];
    __shared__ float nrI[TILE];   // not_root for bi-tile (cols of Q)
    __shared__ float nrJ[TILE];   // not_root for bj-tile (cols of P)

    // Root loads first (tiny, L2-resident).
    if (tid < 2 * TILE) {
        int local = tid & (TILE - 1);
        int base  = (tid < TILE) ? bi : bj;
        int g     = base * TILE + local;
        float p   = rootp[g];
        float2 gr = groot[g];
        float nr  = ((p + gr.x) > (1.0f - p + gr.y)) ? 0.0f : 1.0f;
        if (tid < TILE) nrI[local] = nr; else nrJ[local] = nr;
    }

    // ---- Phase A: tile P(bi,bj). 12 front-batched float4 loads ----
    float4 eP[4], gP0[4], gP1[4];
    const int colPg = bj * 16 + tx;           // float4 col index
    #pragma unroll
    for (int r = 0; r < 4; r++) {
        int rowP = bi * TILE + ty + 16 * r;
        eP[r]  = edgep4[(long)rowP * n4 + colPg];
        long gi = (long)rowP * n2 + (colPg << 1);
        gP0[r] = gedge4[gi];
        gP1[r] = gedge4[gi + 1];
    }

    __syncthreads();   // nrJ/nrI ready

    float v[4][4];
    #pragma unroll
    for (int r = 0; r < 4; r++) {
        int lr = ty + 16 * r;
        v[r][0] = (((eP[r].x + gP0[r].x) > (1.0f - eP[r].x + gP0[r].y)) ? 1.0f : 0.0f) * nrJ[c4 + 0];
        v[r][1] = (((eP[r].y + gP0[r].z) > (1.0f - eP[r].y + gP0[r].w)) ? 1.0f : 0.0f) * nrJ[c4 + 1];
        v[r][2] = (((eP[r].z + gP1[r].x) > (1.0f - eP[r].z + gP1[r].y)) ? 1.0f : 0.0f) * nrJ[c4 + 2];
        v[r][3] = (((eP[r].w + gP1[r].z) > (1.0f - eP[r].w + gP1[r].w)) ? 1.0f : 0.0f) * nrJ[c4 + 3];
        vP[lr][c4 + 0] = v[r][0];
        vP[lr][c4 + 1] = v[r][1];
        vP[lr][c4 + 2] = v[r][2];
        vP[lr][c4 + 3] = v[r][3];
        if (!diag) {
            int rowP = bi * TILE + lr;
            out4[(long)rowP * n4 + colPg] = make_float4(v[r][0], v[r][1], v[r][2], v[r][3]);
        }
    }

    if (!diag) {
        // ---- Phase B loads issued BEFORE the barrier (overlap barrier wait) ----
        float4 eQ[4], gQ0[4], gQ1[4];
        const int colQg = bi * 16 + tx;
        #pragma unroll
        for (int r = 0; r < 4; r++) {
            int rowQ = bj * TILE + ty + 16 * r;
            eQ[r]  = edgep4[(long)rowQ * n4 + colQg];
            long gi = (long)rowQ * n2 + (colQg << 1);
            gQ0[r] = gedge4[gi];
            gQ1[r] = gedge4[gi + 1];
        }

        __syncthreads();   // vP fully written

        #pragma unroll
        for (int r = 0; r < 4; r++) {
            int lr = ty + 16 * r;
            float q0 = (((eQ[r].x + gQ0[r].x) > (1.0f - eQ[r].x + gQ0[r].y)) ? 1.0f : 0.0f) * nrI[c4 + 0];
            float q1 = (((eQ[r].y + gQ0[r].z) > (1.0f - eQ[r].y + gQ0[r].w)) ? 1.0f : 0.0f) * nrI[c4 + 1];
            float q2 = (((eQ[r].z + gQ1[r].x) > (1.0f - eQ[r].z + gQ1[r].y)) ? 1.0f : 0.0f) * nrI[c4 + 2];
            float q3 = (((eQ[r].w + gQ1[r].z) > (1.0f - eQ[r].w + gQ1[r].w)) ? 1.0f : 0.0f) * nrI[c4 + 3];
            float o0 = q0 * (1.0f - vP[c4 + 0][lr]);
            float o1 = q1 * (1.0f - vP[c4 + 1][lr]);
            float o2 = q2 * (1.0f - vP[c4 + 2][lr]);
            float o3 = q3 * (1.0f - vP[c4 + 3][lr]);
            int rowQ = bj * TILE + lr;
            out4[(long)rowQ * n4 + colQg] = make_float4(o0, o1, o2, o3);
        }
    } else {
        __syncthreads();   // vP fully written

        #pragma unroll
        for (int r = 0; r < 4; r++) {
            int lr = ty + 16 * r;
            float o[4];
            #pragma unroll
            for (int k = 0; k < 4; k++) {
                int cc = c4 + k;
                float val = v[r][k];
                if (cc < lr)       val = val * (1.0f - vP[cc][lr]);
                else if (cc == lr) val = 0.0f;
                o[k] = val;
            }
            int rowP = bi * TILE + lr;
            out4[(long)rowP * n4 + colPg] = make_float4(o[0], o[1], o[2], o[3]);
        }
    }
}

extern "C" void kernel_launch(void* const* d_in, const int* in_sizes, int n_in,
                              void* d_out, int out_size) {
    const float*  rootp  = (const float*)d_in[0];
    const float4* edgep4 = (const float4*)d_in[1];
    const float2* groot  = (const float2*)d_in[2];
    const float4* gedge4 = (const float4*)d_in[3];
    float4* out = (float4*)d_out;
    int n = in_sizes[0];
    int T = n / TILE;
    int nblk = T * (T + 1) / 2;

    dag_pair_kernel<<<nblk, 256>>>(rootp, edgep4, groot, gedge4, out, n, T);
}